// round 16
// baseline (speedup 1.0000x reference)
#include <cuda_runtime.h>
#include <math_constants.h>
#include <stdint.h>

#define N_PTS   100000
#define TILE    2048
#define NTILES  49
#define N_PAD   (TILE*NTILES)      // 100352
#define S_SAMP  16384
#define KK      16
#define CH      128
#define NROWS   (S_SAMP*KK)        // 262144
#define FPS_T   256
#define PPT_MAX 4
#define STAT_CTAS 512
#define STAT_ROWS (NROWS/STAT_CTAS) // 512
#define GEMM_SMEM ((CH*CH*2 + 2*CH)*4)

// ---------------- scratch (static device globals: no runtime allocation) ----------------
__device__ unsigned long long g_ckey[256];   // per-block FPS candidate key (0 = empty)
__device__ float4             g_cxyz[256];   // per-block FPS candidate coords
__device__ float              g_bcx, g_bcy, g_bcz;   // broadcast winner coords
__device__ unsigned int       g_bctag;               // broadcast tag = it+1
__device__ float              g_spts[S_SAMP*3];
__device__ float4             g_pt4[N_PAD];
__device__ int                g_knn[NROWS];
__device__ float              g_Y1[(size_t)NROWS*CH];
__device__ float              g_Y2[(size_t)NROWS*CH];
__device__ float              g_psum[STAT_CTAS*CH];
__device__ float              g_psq[STAT_CTAS*CH];
__device__ float              g_scale1[CH], g_shift1[CH], g_scale2[CH], g_shift2[CH];

// ---------------- acquire/release helpers (gpu scope) ------------------------------------
__device__ __forceinline__ unsigned long long ld_acq_u64(const unsigned long long* p) {
    unsigned long long v;
    asm volatile("ld.global.acquire.gpu.u64 %0, [%1];" : "=l"(v) : "l"(p) : "memory");
    return v;
}
__device__ __forceinline__ void st_rel_u64(unsigned long long* p, unsigned long long v) {
    asm volatile("st.global.release.gpu.u64 [%0], %1;" :: "l"(p), "l"(v) : "memory");
}
__device__ __forceinline__ unsigned int ld_acq_u32(const unsigned int* p) {
    unsigned int v;
    asm volatile("ld.global.acquire.gpu.u32 %0, [%1];" : "=r"(v) : "l"(p) : "memory");
    return v;
}
__device__ __forceinline__ void st_rel_u32(unsigned int* p, unsigned int v) {
    asm volatile("st.global.release.gpu.u32 [%0], %1;" :: "l"(p), "r"(v) : "memory");
}

// ---------------- prep: build float4(x,y,z,p2) table, reset FPS sync state ----------------
// p2 uses the PLAIN C expression (R2-verbatim): nvcc's contraction of this exact pattern is
// certified equal to the reference's sum-of-squares emission by the bit-exact FPS output.
__global__ void prep_kernel(const float* __restrict__ pts) {
    int i = blockIdx.x * blockDim.x + threadIdx.x;
    if (i < N_PTS) {
        float x = pts[3*i], y = pts[3*i+1], z = pts[3*i+2];
        g_pt4[i] = make_float4(x, y, z, x*x + y*y + z*z);
    } else if (i < N_PAD) {
        g_pt4[i] = make_float4(0.f, 0.f, 0.f, 1e30f);   // sentinel: finite, huge distance
    }
    if (i < 256) g_ckey[i] = 0ull;
    if (i == 0)  g_bctag = 0u;
}

// ---------------- FPS: persistent grid, release/acquire handshake, no atomics ------------
// (verified bit-exact vs reference over all 16384 samples -- do not perturb arithmetic)
__global__ void __launch_bounds__(FPS_T) fps_kernel(const float* __restrict__ pts,
                                                    float* __restrict__ out_sp) {
    const int tid   = threadIdx.x;
    const int nb    = gridDim.x;
    const int total = nb * FPS_T;
    const int gt    = blockIdx.x * FPS_T + tid;

    float px[PPT_MAX], py[PPT_MAX], pz[PPT_MAX], md[PPT_MAX];
#pragma unroll
    for (int k = 0; k < PPT_MAX; k++) {
        int g = gt + k * total;
        if (g < N_PTS) {
            px[k] = pts[3*g]; py[k] = pts[3*g+1]; pz[k] = pts[3*g+2];
            md[k] = 1e10f;                       // matches reference init
        } else {
            px[k] = 0.f; py[k] = 0.f; pz[k] = 0.f;
            md[k] = -1.f;                        // invalid slot: stays negative forever
        }
    }

    __shared__ float s_l[3];
    __shared__ unsigned long long s_w[FPS_T/32];  // local block reduce
    __shared__ unsigned long long s_r[FPS_T/32];  // block0 global reduce

    float lx = pts[0], ly = pts[1], lz = pts[2]; // first center = index 0

    for (int it = 0; it < S_SAMP; it++) {
        if (blockIdx.x == 0 && tid == 0) {
            out_sp[3*it+0] = lx; out_sp[3*it+1] = ly; out_sp[3*it+2] = lz;
            g_spts[3*it+0] = lx; g_spts[3*it+1] = ly; g_spts[3*it+2] = lz;
        }
        // update min_d; local argmax (packed key: larger d wins, tie -> smaller idx)
        unsigned long long best = 0ull;
        float bx = 0.f, by = 0.f, bz = 0.f;
#pragma unroll
        for (int k = 0; k < PPT_MAX; k++) {
            float dx = px[k]-lx, dy = py[k]-ly, dz = pz[k]-lz;
            float d  = dx*dx + dy*dy + dz*dz;
            float m  = fminf(md[k], d);
            md[k] = m;
            if (m >= 0.f) {
                unsigned long long key =
                    ((unsigned long long)__float_as_uint(m) << 32) |
                    (unsigned long long)(unsigned)(~(unsigned)(gt + k*total));
                if (key > best) { best = key; bx = px[k]; by = py[k]; bz = pz[k]; }
            }
        }
        // warp max (lane 0 holds the true max)
        unsigned long long wk = best;
#pragma unroll
        for (int off = 16; off > 0; off >>= 1) {
            unsigned long long o = __shfl_down_sync(0xFFFFFFFFu, wk, off);
            if (o > wk) wk = o;
        }
        if ((tid & 31) == 0) s_w[tid >> 5] = wk;
        __syncthreads();                                             // (A)
        unsigned long long blockbest = s_w[0];
#pragma unroll
        for (int w = 1; w < FPS_T/32; w++) if (s_w[w] > blockbest) blockbest = s_w[w];
        // the unique thread owning blockbest publishes the block candidate
        if (best == blockbest && best != 0ull) {
            g_cxyz[blockIdx.x] = make_float4(bx, by, bz, 0.f);
            st_rel_u64(&g_ckey[blockIdx.x], best);                   // release: xyz first
        }

        if (blockIdx.x == 0) {
            unsigned long long k2 = 0ull;
            float4 cxyz = make_float4(0.f, 0.f, 0.f, 0.f);
            if (tid < nb) {
                do { k2 = ld_acq_u64(&g_ckey[tid]); } while (k2 == 0ull);
                cxyz = g_cxyz[tid];          // ordered after the acquire
                g_ckey[tid] = 0ull;          // reset; ordered before tag via (B)+release
            }
            unsigned long long gk = k2;
#pragma unroll
            for (int off = 16; off > 0; off >>= 1) {
                unsigned long long o = __shfl_down_sync(0xFFFFFFFFu, gk, off);
                if (o > gk) gk = o;
            }
            if ((tid & 31) == 0) s_r[tid >> 5] = gk;
            __syncthreads();                                         // (B)
            unsigned long long gbest = s_r[0];
#pragma unroll
            for (int w = 1; w < FPS_T/32; w++) if (s_r[w] > gbest) gbest = s_r[w];
            if (tid < nb && k2 == gbest) {   // unique winner thread publishes broadcast
                g_bcx = cxyz.x; g_bcy = cxyz.y; g_bcz = cxyz.z;
                st_rel_u32(&g_bctag, (unsigned)(it + 1));
            }
        }

        if (tid == 0) {
            while (ld_acq_u32(&g_bctag) != (unsigned)(it + 1)) { }
            s_l[0] = g_bcx; s_l[1] = g_bcy; s_l[2] = g_bcz;
        }
        __syncthreads();                                             // (C)
        lx = s_l[0]; ly = s_l[1]; lz = s_l[2];
    }
}

// ---------------- kNN: 128 queries/CTA, 2 threads per query, smem point tiles ------------
// Tree (unique cell consistent with R2/R15, R10, R11/R14 flip algebra; the cell R12 was
// SUPPOSED to test but provably never ran):
//   p2, q2 : PLAIN C `x*x + y*y + z*z` (nvcc contraction == ref, certified by FPS)
//   dot    : UNCONTRACTED  add(add(mul(qx,vx), mul(qy,vy)), mul(qz,vz))
//            (XLA rewrites the K=3 matmul to broadcast-mul + reduce; the reduce combiner
//             is a separate add that LLVM cannot fold into fmuladd)
//   d      : fmaf(dot, -2, q2 + p2)  ==  sub(add(q2,p2), mul(2,dot))  [2*dot exact]
__device__ __forceinline__ bool knn_less(float d1, int i1, float d2, int i2) {
    return (d1 < d2) || (d1 == d2 && i1 < i2);
}

__global__ void __launch_bounds__(256) knn_kernel(void) {
    __shared__ float4 s_tile[TILE];   // 32KB; aliased for the merge phase afterwards
    const int tid  = threadIdx.x;
    const int ql   = tid & 127;
    const int half = tid >> 7;
    const int q    = blockIdx.x * 128 + ql;

    const float qx = g_spts[3*q], qy = g_spts[3*q+1], qz = g_spts[3*q+2];
    const float q2 = qx*qx + qy*qy + qz*qz;   // R2-verbatim (nvcc-contracted like FPS/ref)

    float dq[KK]; int iq[KK];
#pragma unroll
    for (int j = 0; j < KK; j++) { dq[j] = CUDART_INF_F; iq[j] = 0x7FFFFFFF; }

    for (int t = 0; t < NTILES; t++) {
#pragma unroll
        for (int i = 0; i < TILE/256; i++)
            s_tile[tid + i*256] = g_pt4[t*TILE + tid + i*256];
        __syncthreads();

        const int base = half * (TILE/2);
#pragma unroll 4
        for (int p = 0; p < TILE/2; p++) {
            float4 v  = s_tile[base + p];
            float dot = __fadd_rn(__fadd_rn(__fmul_rn(qx, v.x), __fmul_rn(qy, v.y)),
                                  __fmul_rn(qz, v.z));
            float d   = fmaf(dot, -2.0f, q2 + v.w);
            int gidx  = t*TILE + base + p;
            if (knn_less(d, gidx, dq[KK-1], iq[KK-1])) {
#pragma unroll
                for (int m = KK-1; m >= 0; m--) {
                    bool lt = knn_less(d, gidx, dq[m], iq[m]);
                    if (lt) {
                        if (m < KK-1) { dq[m+1] = dq[m]; iq[m+1] = iq[m]; }
                        dq[m] = d; iq[m] = gidx;
                    }
                }
            }
        }
        __syncthreads();
    }

    // merge the two halves' top-16 lists (alias tile smem)
    float* mD = (float*)s_tile;                 // 2*128*16 floats = 16KB
    int*   mI = (int*)(mD + 2*128*KK);          // 16KB
#pragma unroll
    for (int j = 0; j < KK; j++) {
        mD[(half*128 + ql)*KK + j] = dq[j];
        mI[(half*128 + ql)*KK + j] = iq[j];
    }
    __syncthreads();
    if (half == 0) {
        const float* dA = &mD[ql*KK];        const int* iA = &mI[ql*KK];
        const float* dB = &mD[(128+ql)*KK];  const int* iB = &mI[(128+ql)*KK];
        int a = 0, b = 0;
        int* outI = &g_knn[(size_t)q*KK];
#pragma unroll
        for (int j = 0; j < KK; j++) {
            bool takeB = knn_less(dB[b], iB[b], dA[a], iA[a]);
            if (takeB) { outI[j] = iB[b]; b++; }
            else       { outI[j] = iA[a]; a++; }
        }
    }
}

// ---------------- GEMM: 128x128x128 tile, 8x8 register blocking, fp32 -------------------
// gather!=0: rows gathered via g_knn from `src` (features).
// scale!=NULL: apply y = relu(x*scale+shift) while filling the A tile (BN+ReLU fused).
// fp32 fma accumulation ascending in k -- same order as cuBLAS SIMT sgemm.
__global__ void __launch_bounds__(256) gemm_kernel(const float* __restrict__ src,
                                                   const float* __restrict__ W,
                                                   const float* __restrict__ scale,
                                                   const float* __restrict__ shift,
                                                   float* __restrict__ outY,
                                                   int gather) {
    extern __shared__ float sm[];
    float* Xs = sm;               // [k][row], 128*128
    float* Ws = sm + CH*CH;       // [k][col], 128*128
    float* Sc = Ws + CH*CH;       // 128
    float* Sh = Sc + CH;          // 128
    const int tid = threadIdx.x;
    const size_t rbase = (size_t)blockIdx.x * CH;

    {   // load W (64KB) cooperatively
        const float4* W4 = (const float4*)W;
        float4* Ws4 = (float4*)Ws;
#pragma unroll
        for (int i = 0; i < 16; i++) Ws4[tid + i*256] = W4[tid + i*256];
    }
    if (scale && tid < CH) { Sc[tid] = scale[tid]; Sh[tid] = shift[tid]; }
    __syncthreads();

    // fill A tile (transposed into [k][row]); BN+ReLU fused when scale != NULL
    const int row = tid >> 1, hf = tid & 1;
    const float* srow;
    if (gather) srow = src + (size_t)g_knn[rbase + row] * CH;
    else        srow = src + (rbase + row) * CH;
    const float4* s4 = (const float4*)srow + hf*16;
#pragma unroll
    for (int i = 0; i < 16; i++) {
        float4 v = s4[i];
        int c = hf*64 + i*4;
        if (scale) {
            v.x = fmaxf(fmaf(v.x, Sc[c+0], Sh[c+0]), 0.f);
            v.y = fmaxf(fmaf(v.y, Sc[c+1], Sh[c+1]), 0.f);
            v.z = fmaxf(fmaf(v.z, Sc[c+2], Sh[c+2]), 0.f);
            v.w = fmaxf(fmaf(v.w, Sc[c+3], Sh[c+3]), 0.f);
        }
        Xs[(c+0)*CH + row] = v.x;
        Xs[(c+1)*CH + row] = v.y;
        Xs[(c+2)*CH + row] = v.z;
        Xs[(c+3)*CH + row] = v.w;
    }
    __syncthreads();

    const int tx = tid & 15, ty = tid >> 4;
    const int r0 = ty*8, c0 = tx*8;
    float acc[8][8];
#pragma unroll
    for (int i = 0; i < 8; i++)
#pragma unroll
        for (int j = 0; j < 8; j++) acc[i][j] = 0.f;

#pragma unroll 2
    for (int k = 0; k < CH; k++) {
        float a[8], b[8];
        *(float4*)&a[0] = *(const float4*)&Xs[k*CH + r0];
        *(float4*)&a[4] = *(const float4*)&Xs[k*CH + r0 + 4];
        *(float4*)&b[0] = *(const float4*)&Ws[k*CH + c0];
        *(float4*)&b[4] = *(const float4*)&Ws[k*CH + c0 + 4];
#pragma unroll
        for (int i = 0; i < 8; i++)
#pragma unroll
            for (int j = 0; j < 8; j++) acc[i][j] = fmaf(a[i], b[j], acc[i][j]);
    }
#pragma unroll
    for (int i = 0; i < 8; i++) {
        float* yr = outY + (rbase + r0 + i)*CH + c0;
        *(float4*)yr     = *(float4*)&acc[i][0];
        *(float4*)(yr+4) = *(float4*)&acc[i][4];
    }
}

// ---------------- BN stats: deterministic two-level reduction ----------------------------
__global__ void __launch_bounds__(256) stats_part_kernel(const float* __restrict__ Y) {
    const int tid = threadIdx.x;
    const int col = tid & 127, hf = tid >> 7;   // 2 threads per column
    const size_t base = (size_t)blockIdx.x * STAT_ROWS * CH;
    float s = 0.f, q = 0.f;
    for (int r = hf; r < STAT_ROWS; r += 2) {
        float v = Y[base + (size_t)r*CH + col];
        s += v;
        q = fmaf(v, v, q);
    }
    __shared__ float sh[512];
    sh[tid] = s; sh[256 + tid] = q;
    __syncthreads();
    if (hf == 0) {
        g_psum[blockIdx.x*CH + col] = s + sh[tid + 128];
        g_psq [blockIdx.x*CH + col] = q + sh[256 + tid + 128];
    }
}

__global__ void stats_final_kernel(const float* __restrict__ gamma,
                                   const float* __restrict__ beta,
                                   float* __restrict__ scale,
                                   float* __restrict__ shift) {
    int c = threadIdx.x;  // 128 threads
    float s = 0.f, q = 0.f;
    for (int i = 0; i < STAT_CTAS; i++) { s += g_psum[i*CH + c]; q += g_psq[i*CH + c]; }
    const float inv_n = 1.0f / (float)NROWS;
    float mean = s * inv_n;
    float var  = q * inv_n - mean*mean;
    float sc   = gamma[c] / sqrtf(var + 1e-5f);
    scale[c] = sc;
    shift[c] = fmaf(-mean, sc, beta[c]);
}

// ---------------- finalize: BN + ReLU + max-pool over K ---------------------------------
__global__ void __launch_bounds__(128) finalize_kernel(float* __restrict__ out) {
    const int s = blockIdx.x, c = threadIdx.x;
    const float sc = g_scale2[c], sh = g_shift2[c];
    const float* y = g_Y2 + (size_t)s*KK*CH + c;
    float m = 0.f;                       // relu >= 0, so 0 is the correct identity
#pragma unroll
    for (int k = 0; k < KK; k++) {
        float v = fmaf(y[(size_t)k*CH], sc, sh);
        m = fmaxf(m, v);
    }
    out[(size_t)S_SAMP*3 + (size_t)s*CH + c] = m;
}

// ---------------- launch ----------------------------------------------------------------
extern "C" void kernel_launch(void* const* d_in, const int* in_sizes, int n_in,
                              void* d_out, int out_size) {
    const float* points   = (const float*)d_in[0];
    const float* features = (const float*)d_in[1];
    const float* W1 = (const float*)d_in[2];
    const float* g1 = (const float*)d_in[3];
    const float* b1 = (const float*)d_in[4];
    const float* W2 = (const float*)d_in[5];
    const float* g2 = (const float*)d_in[6];
    const float* b2 = (const float*)d_in[7];
    float* out = (float*)d_out;

    int sms = 148;
    cudaDeviceGetAttribute(&sms, cudaDevAttrMultiProcessorCount, 0);
    if (sms > 256) sms = 256;           // g_ckey/g_cxyz sized 256; PPT covers nb >= 98

    cudaFuncSetAttribute(gemm_kernel, cudaFuncAttributeMaxDynamicSharedMemorySize, GEMM_SMEM);

    void *y1p = 0, *y2p = 0, *sc1 = 0, *sh1 = 0, *sc2 = 0, *sh2 = 0;
    cudaGetSymbolAddress(&y1p, g_Y1);
    cudaGetSymbolAddress(&y2p, g_Y2);
    cudaGetSymbolAddress(&sc1, g_scale1);
    cudaGetSymbolAddress(&sh1, g_shift1);
    cudaGetSymbolAddress(&sc2, g_scale2);
    cudaGetSymbolAddress(&sh2, g_shift2);

    prep_kernel<<<(N_PAD + 255)/256, 256>>>(points);
    fps_kernel<<<sms, FPS_T>>>(points, out);
    knn_kernel<<<S_SAMP/128, 256>>>();
    gemm_kernel<<<NROWS/CH, 256, GEMM_SMEM>>>(features, W1, nullptr, nullptr,
                                              (float*)y1p, 1);
    stats_part_kernel<<<STAT_CTAS, 256>>>((const float*)y1p);
    stats_final_kernel<<<1, 128>>>(g1, b1, (float*)sc1, (float*)sh1);
    gemm_kernel<<<NROWS/CH, 256, GEMM_SMEM>>>((const float*)y1p, W2,
                                              (const float*)sc1, (const float*)sh1,
                                              (float*)y2p, 0);
    stats_part_kernel<<<STAT_CTAS, 256>>>((const float*)y2p);
    stats_final_kernel<<<1, 128>>>(g2, b2, (float*)sc2, (float*)sh2);
    finalize_kernel<<<S_SAMP, 128>>>(out);
}

// round 17
// speedup vs baseline: 1.1312x; 1.1312x over previous
#include <cuda_runtime.h>
#include <math_constants.h>
#include <stdint.h>

#define N_PTS   100000
#define TILE    2048
#define NTILES  49
#define N_PAD   (TILE*NTILES)      // 100352
#define S_SAMP  16384
#define KK      16
#define CH      128
#define NROWS   (S_SAMP*KK)        // 262144
#define FPS_T   256
#define PPT_MAX 4
#define STAT_CTAS 512
#define STAT_ROWS (NROWS/STAT_CTAS) // 512
#define GEMM_SMEM ((CH*CH*2 + 2*CH)*4)

// ---------------- scratch (static device globals: no runtime allocation) ----------------
// FPS broadcast line: one 128B line per (parity, block). tag is release-stored last and
// acquire-loaded first; payload (key,x,y,z) is ordered by the tag. Epochs are monotonic,
// so no resets are needed across iterations; prep re-zeros tags per launch.
struct __align__(128) PayLine {
    unsigned int        tag;      // = it+1 when iteration it's candidate is published
    unsigned int        pad0;
    unsigned long long  key;      // (f32 min_d bits << 32) | ~idx   (max = winner)
    float               x, y, z;
    unsigned char       pad[128 - 8 - 8 - 12];
};
__device__ PayLine g_pay[2][256];

__device__ float              g_spts[S_SAMP*3];
__device__ float4             g_pt4[N_PAD];
__device__ int                g_knn[NROWS];
__device__ float              g_Y1[(size_t)NROWS*CH];
__device__ float              g_Y2[(size_t)NROWS*CH];
__device__ float              g_psum[STAT_CTAS*CH];
__device__ float              g_psq[STAT_CTAS*CH];
__device__ float              g_scale1[CH], g_shift1[CH], g_scale2[CH], g_shift2[CH];

// ---------------- acquire/release helpers (gpu scope) ------------------------------------
__device__ __forceinline__ unsigned int ld_acq_u32(const unsigned int* p) {
    unsigned int v;
    asm volatile("ld.global.acquire.gpu.u32 %0, [%1];" : "=r"(v) : "l"(p) : "memory");
    return v;
}
__device__ __forceinline__ void st_rel_u32(unsigned int* p, unsigned int v) {
    asm volatile("st.global.release.gpu.u32 [%0], %1;" :: "l"(p), "r"(v) : "memory");
}

// ---------------- prep: build float4(x,y,z,p2) table, reset FPS sync state ----------------
// p2 uses the PLAIN C expression: nvcc's contraction of this exact pattern is certified
// equal to the reference's sum-of-squares emission by the bit-exact FPS output (R2..R16).
__global__ void prep_kernel(const float* __restrict__ pts) {
    int i = blockIdx.x * blockDim.x + threadIdx.x;
    if (i < N_PTS) {
        float x = pts[3*i], y = pts[3*i+1], z = pts[3*i+2];
        g_pt4[i] = make_float4(x, y, z, x*x + y*y + z*z);
    } else if (i < N_PAD) {
        g_pt4[i] = make_float4(0.f, 0.f, 0.f, 1e30f);   // sentinel: finite, huge distance
    }
    if (i < 256) { g_pay[0][i].tag = 0u; g_pay[1][i].tag = 0u; }
}

// ---------------- FPS: persistent grid, SINGLE-HOP epoch broadcast -----------------------
// Per iteration: each block computes its local argmax candidate (identical partition and
// arithmetic to the verified bit-exact version); the block-winning thread writes
// {key,x,y,z} to its own 128B line and release-stores tag=it+1 (double-buffered by
// iteration parity). Then EVERY block's threads 0..nb-1 acquire-spin on the 148 tags in
// parallel (one line per thread -> no hotspot), read the payloads, and block-reduce the
// max key locally. All blocks see the same key set -> same winner -> same next center.
// No second broadcast hop, no resets. Candidate set + (max d, min idx) tie-break are
// unchanged, so the sample sequence is bit-identical to the passing R16 kernel.
__global__ void __launch_bounds__(FPS_T) fps_kernel(const float* __restrict__ pts,
                                                    float* __restrict__ out_sp) {
    const int tid   = threadIdx.x;
    const int nb    = gridDim.x;
    const int total = nb * FPS_T;
    const int gt    = blockIdx.x * FPS_T + tid;

    float px[PPT_MAX], py[PPT_MAX], pz[PPT_MAX], md[PPT_MAX];
#pragma unroll
    for (int k = 0; k < PPT_MAX; k++) {
        int g = gt + k * total;
        if (g < N_PTS) {
            px[k] = pts[3*g]; py[k] = pts[3*g+1]; pz[k] = pts[3*g+2];
            md[k] = 1e10f;                       // matches reference init
        } else {
            px[k] = 0.f; py[k] = 0.f; pz[k] = 0.f;
            md[k] = -1.f;                        // invalid slot: stays negative forever
        }
    }

    __shared__ float s_l[3];
    __shared__ unsigned long long s_w[FPS_T/32];  // local block reduce
    __shared__ unsigned long long s_r[FPS_T/32];  // global candidate reduce

    float lx = pts[0], ly = pts[1], lz = pts[2]; // first center = index 0

    for (int it = 0; it < S_SAMP; it++) {
        if (blockIdx.x == 0 && tid == 0) {
            out_sp[3*it+0] = lx; out_sp[3*it+1] = ly; out_sp[3*it+2] = lz;
            g_spts[3*it+0] = lx; g_spts[3*it+1] = ly; g_spts[3*it+2] = lz;
        }
        // update min_d; local argmax (packed key: larger d wins, tie -> smaller idx)
        unsigned long long best = 0ull;
        float bx = 0.f, by = 0.f, bz = 0.f;
#pragma unroll
        for (int k = 0; k < PPT_MAX; k++) {
            float dx = px[k]-lx, dy = py[k]-ly, dz = pz[k]-lz;
            float d  = dx*dx + dy*dy + dz*dz;
            float m  = fminf(md[k], d);
            md[k] = m;
            if (m >= 0.f) {
                unsigned long long key =
                    ((unsigned long long)__float_as_uint(m) << 32) |
                    (unsigned long long)(unsigned)(~(unsigned)(gt + k*total));
                if (key > best) { best = key; bx = px[k]; by = py[k]; bz = pz[k]; }
            }
        }
        // warp max (lane 0 holds the true max)
        unsigned long long wk = best;
#pragma unroll
        for (int off = 16; off > 0; off >>= 1) {
            unsigned long long o = __shfl_down_sync(0xFFFFFFFFu, wk, off);
            if (o > wk) wk = o;
        }
        if ((tid & 31) == 0) s_w[tid >> 5] = wk;
        __syncthreads();                                             // (A)
        unsigned long long blockbest = s_w[0];
#pragma unroll
        for (int w = 1; w < FPS_T/32; w++) if (s_w[w] > blockbest) blockbest = s_w[w];
        // the unique thread owning blockbest publishes the block candidate
        if (best == blockbest && best != 0ull) {
            PayLine* L = &g_pay[it & 1][blockIdx.x];
            L->key = best; L->x = bx; L->y = by; L->z = bz;
            st_rel_u32(&L->tag, (unsigned)(it + 1));                 // release: payload first
        }

        // every block gathers all candidates itself (single hop, parallel detect)
        unsigned long long k2 = 0ull;
        float cx = 0.f, cy = 0.f, cz = 0.f;
        if (tid < nb) {
            PayLine* L = &g_pay[it & 1][tid];
            while (ld_acq_u32(&L->tag) < (unsigned)(it + 1)) { }
            k2 = L->key; cx = L->x; cy = L->y; cz = L->z;
        }
        unsigned long long gk = k2;
#pragma unroll
        for (int off = 16; off > 0; off >>= 1) {
            unsigned long long o = __shfl_down_sync(0xFFFFFFFFu, gk, off);
            if (o > gk) gk = o;
        }
        if ((tid & 31) == 0) s_r[tid >> 5] = gk;
        __syncthreads();                                             // (B)
        unsigned long long gbest = s_r[0];
#pragma unroll
        for (int w = 1; w < FPS_T/32; w++) if (s_r[w] > gbest) gbest = s_r[w];
        if (tid < nb && k2 == gbest) {   // unique owner broadcasts coords via smem
            s_l[0] = cx; s_l[1] = cy; s_l[2] = cz;
        }
        __syncthreads();                                             // (C)
        lx = s_l[0]; ly = s_l[1]; lz = s_l[2];
    }
}

// ---------------- kNN: 128 queries/CTA, 2 threads per query, smem point tiles ------------
// FROZEN tree (verified PASS in R16):
//   p2, q2 : PLAIN C `x*x + y*y + z*z` (nvcc-contracted, == ref)
//   dot    : UNCONTRACTED  add(add(mul(qx,vx), mul(qy,vy)), mul(qz,vz))
//   d      : fmaf(dot, -2, q2 + p2)
__device__ __forceinline__ bool knn_less(float d1, int i1, float d2, int i2) {
    return (d1 < d2) || (d1 == d2 && i1 < i2);
}

__global__ void __launch_bounds__(256) knn_kernel(void) {
    __shared__ float4 s_tile[TILE];   // 32KB; aliased for the merge phase afterwards
    const int tid  = threadIdx.x;
    const int ql   = tid & 127;
    const int half = tid >> 7;
    const int q    = blockIdx.x * 128 + ql;

    const float qx = g_spts[3*q], qy = g_spts[3*q+1], qz = g_spts[3*q+2];
    const float q2 = qx*qx + qy*qy + qz*qz;

    float dq[KK]; int iq[KK];
#pragma unroll
    for (int j = 0; j < KK; j++) { dq[j] = CUDART_INF_F; iq[j] = 0x7FFFFFFF; }

    for (int t = 0; t < NTILES; t++) {
#pragma unroll
        for (int i = 0; i < TILE/256; i++)
            s_tile[tid + i*256] = g_pt4[t*TILE + tid + i*256];
        __syncthreads();

        const int base = half * (TILE/2);
#pragma unroll 4
        for (int p = 0; p < TILE/2; p++) {
            float4 v  = s_tile[base + p];
            float dot = __fadd_rn(__fadd_rn(__fmul_rn(qx, v.x), __fmul_rn(qy, v.y)),
                                  __fmul_rn(qz, v.z));
            float d   = fmaf(dot, -2.0f, q2 + v.w);
            int gidx  = t*TILE + base + p;
            if (knn_less(d, gidx, dq[KK-1], iq[KK-1])) {
#pragma unroll
                for (int m = KK-1; m >= 0; m--) {
                    bool lt = knn_less(d, gidx, dq[m], iq[m]);
                    if (lt) {
                        if (m < KK-1) { dq[m+1] = dq[m]; iq[m+1] = iq[m]; }
                        dq[m] = d; iq[m] = gidx;
                    }
                }
            }
        }
        __syncthreads();
    }

    // merge the two halves' top-16 lists (alias tile smem)
    float* mD = (float*)s_tile;                 // 2*128*16 floats = 16KB
    int*   mI = (int*)(mD + 2*128*KK);          // 16KB
#pragma unroll
    for (int j = 0; j < KK; j++) {
        mD[(half*128 + ql)*KK + j] = dq[j];
        mI[(half*128 + ql)*KK + j] = iq[j];
    }
    __syncthreads();
    if (half == 0) {
        const float* dA = &mD[ql*KK];        const int* iA = &mI[ql*KK];
        const float* dB = &mD[(128+ql)*KK];  const int* iB = &mI[(128+ql)*KK];
        int a = 0, b = 0;
        int* outI = &g_knn[(size_t)q*KK];
#pragma unroll
        for (int j = 0; j < KK; j++) {
            bool takeB = knn_less(dB[b], iB[b], dA[a], iA[a]);
            if (takeB) { outI[j] = iB[b]; b++; }
            else       { outI[j] = iA[a]; a++; }
        }
    }
}

// ---------------- GEMM: 128x128x128 tile, 8x8 register blocking, fp32 -------------------
// gather!=0: rows gathered via g_knn from `src` (features).
// scale!=NULL: apply y = relu(x*scale+shift) while filling the A tile (BN+ReLU fused).
__global__ void __launch_bounds__(256) gemm_kernel(const float* __restrict__ src,
                                                   const float* __restrict__ W,
                                                   const float* __restrict__ scale,
                                                   const float* __restrict__ shift,
                                                   float* __restrict__ outY,
                                                   int gather) {
    extern __shared__ float sm[];
    float* Xs = sm;               // [k][row], 128*128
    float* Ws = sm + CH*CH;       // [k][col], 128*128
    float* Sc = Ws + CH*CH;       // 128
    float* Sh = Sc + CH;          // 128
    const int tid = threadIdx.x;
    const size_t rbase = (size_t)blockIdx.x * CH;

    {   // load W (64KB) cooperatively
        const float4* W4 = (const float4*)W;
        float4* Ws4 = (float4*)Ws;
#pragma unroll
        for (int i = 0; i < 16; i++) Ws4[tid + i*256] = W4[tid + i*256];
    }
    if (scale && tid < CH) { Sc[tid] = scale[tid]; Sh[tid] = shift[tid]; }
    __syncthreads();

    // fill A tile (transposed into [k][row]); BN+ReLU fused when scale != NULL
    const int row = tid >> 1, hf = tid & 1;
    const float* srow;
    if (gather) srow = src + (size_t)g_knn[rbase + row] * CH;
    else        srow = src + (rbase + row) * CH;
    const float4* s4 = (const float4*)srow + hf*16;
#pragma unroll
    for (int i = 0; i < 16; i++) {
        float4 v = s4[i];
        int c = hf*64 + i*4;
        if (scale) {
            v.x = fmaxf(fmaf(v.x, Sc[c+0], Sh[c+0]), 0.f);
            v.y = fmaxf(fmaf(v.y, Sc[c+1], Sh[c+1]), 0.f);
            v.z = fmaxf(fmaf(v.z, Sc[c+2], Sh[c+2]), 0.f);
            v.w = fmaxf(fmaf(v.w, Sc[c+3], Sh[c+3]), 0.f);
        }
        Xs[(c+0)*CH + row] = v.x;
        Xs[(c+1)*CH + row] = v.y;
        Xs[(c+2)*CH + row] = v.z;
        Xs[(c+3)*CH + row] = v.w;
    }
    __syncthreads();

    const int tx = tid & 15, ty = tid >> 4;
    const int r0 = ty*8, c0 = tx*8;
    float acc[8][8];
#pragma unroll
    for (int i = 0; i < 8; i++)
#pragma unroll
        for (int j = 0; j < 8; j++) acc[i][j] = 0.f;

#pragma unroll 2
    for (int k = 0; k < CH; k++) {
        float a[8], b[8];
        *(float4*)&a[0] = *(const float4*)&Xs[k*CH + r0];
        *(float4*)&a[4] = *(const float4*)&Xs[k*CH + r0 + 4];
        *(float4*)&b[0] = *(const float4*)&Ws[k*CH + c0];
        *(float4*)&b[4] = *(const float4*)&Ws[k*CH + c0 + 4];
#pragma unroll
        for (int i = 0; i < 8; i++)
#pragma unroll
            for (int j = 0; j < 8; j++) acc[i][j] = fmaf(a[i], b[j], acc[i][j]);
    }
#pragma unroll
    for (int i = 0; i < 8; i++) {
        float* yr = outY + (rbase + r0 + i)*CH + c0;
        *(float4*)yr     = *(float4*)&acc[i][0];
        *(float4*)(yr+4) = *(float4*)&acc[i][4];
    }
}

// ---------------- BN stats: deterministic two-level reduction ----------------------------
__global__ void __launch_bounds__(256) stats_part_kernel(const float* __restrict__ Y) {
    const int tid = threadIdx.x;
    const int col = tid & 127, hf = tid >> 7;   // 2 threads per column
    const size_t base = (size_t)blockIdx.x * STAT_ROWS * CH;
    float s = 0.f, q = 0.f;
    for (int r = hf; r < STAT_ROWS; r += 2) {
        float v = Y[base + (size_t)r*CH + col];
        s += v;
        q = fmaf(v, v, q);
    }
    __shared__ float sh[512];
    sh[tid] = s; sh[256 + tid] = q;
    __syncthreads();
    if (hf == 0) {
        g_psum[blockIdx.x*CH + col] = s + sh[tid + 128];
        g_psq [blockIdx.x*CH + col] = q + sh[256 + tid + 128];
    }
}

__global__ void stats_final_kernel(const float* __restrict__ gamma,
                                   const float* __restrict__ beta,
                                   float* __restrict__ scale,
                                   float* __restrict__ shift) {
    int c = threadIdx.x;  // 128 threads
    float s = 0.f, q = 0.f;
    for (int i = 0; i < STAT_CTAS; i++) { s += g_psum[i*CH + c]; q += g_psq[i*CH + c]; }
    const float inv_n = 1.0f / (float)NROWS;
    float mean = s * inv_n;
    float var  = q * inv_n - mean*mean;
    float sc   = gamma[c] / sqrtf(var + 1e-5f);
    scale[c] = sc;
    shift[c] = fmaf(-mean, sc, beta[c]);
}

// ---------------- finalize: BN + ReLU + max-pool over K ---------------------------------
__global__ void __launch_bounds__(128) finalize_kernel(float* __restrict__ out) {
    const int s = blockIdx.x, c = threadIdx.x;
    const float sc = g_scale2[c], sh = g_shift2[c];
    const float* y = g_Y2 + (size_t)s*KK*CH + c;
    float m = 0.f;                       // relu >= 0, so 0 is the correct identity
#pragma unroll
    for (int k = 0; k < KK; k++) {
        float v = fmaf(y[(size_t)k*CH], sc, sh);
        m = fmaxf(m, v);
    }
    out[(size_t)S_SAMP*3 + (size_t)s*CH + c] = m;
}

// ---------------- launch ----------------------------------------------------------------
extern "C" void kernel_launch(void* const* d_in, const int* in_sizes, int n_in,
                              void* d_out, int out_size) {
    const float* points   = (const float*)d_in[0];
    const float* features = (const float*)d_in[1];
    const float* W1 = (const float*)d_in[2];
    const float* g1 = (const float*)d_in[3];
    const float* b1 = (const float*)d_in[4];
    const float* W2 = (const float*)d_in[5];
    const float* g2 = (const float*)d_in[6];
    const float* b2 = (const float*)d_in[7];
    float* out = (float*)d_out;

    int sms = 148;
    cudaDeviceGetAttribute(&sms, cudaDevAttrMultiProcessorCount, 0);
    if (sms > 256) sms = 256;           // g_pay sized 256; PPT covers nb >= 98

    cudaFuncSetAttribute(gemm_kernel, cudaFuncAttributeMaxDynamicSharedMemorySize, GEMM_SMEM);

    void *y1p = 0, *y2p = 0, *sc1 = 0, *sh1 = 0, *sc2 = 0, *sh2 = 0;
    cudaGetSymbolAddress(&y1p, g_Y1);
    cudaGetSymbolAddress(&y2p, g_Y2);
    cudaGetSymbolAddress(&sc1, g_scale1);
    cudaGetSymbolAddress(&sh1, g_shift1);
    cudaGetSymbolAddress(&sc2, g_scale2);
    cudaGetSymbolAddress(&sh2, g_shift2);

    prep_kernel<<<(N_PAD + 255)/256, 256>>>(points);
    fps_kernel<<<sms, FPS_T>>>(points, out);
    knn_kernel<<<S_SAMP/128, 256>>>();
    gemm_kernel<<<NROWS/CH, 256, GEMM_SMEM>>>(features, W1, nullptr, nullptr,
                                              (float*)y1p, 1);
    stats_part_kernel<<<STAT_CTAS, 256>>>((const float*)y1p);
    stats_final_kernel<<<1, 128>>>(g1, b1, (float*)sc1, (float*)sh1);
    gemm_kernel<<<NROWS/CH, 256, GEMM_SMEM>>>((const float*)y1p, W2,
                                              (const float*)sc1, (const float*)sh1,
                                              (float*)y2p, 0);
    stats_part_kernel<<<STAT_CTAS, 256>>>((const float*)y2p);
    stats_final_kernel<<<1, 128>>>(g2, b2, (float*)sc2, (float*)sh2);
    finalize_kernel<<<S_SAMP, 128>>>(out);
}